// round 15
// baseline (speedup 1.0000x reference)
#include <cuda_runtime.h>
#include <cuda_fp16.h>

#define N_ATOMS 50000
#define N_PAIRS 800000
#define FDIM    128
#define F3      384

// ---------------- scratch (device globals; no runtime allocation) ----------
__device__ int    g_count [N_ATOMS];
__device__ int    g_cursor[N_ATOMS];
__device__ int    g_offset[N_ATOMS + 1];
__device__ int    g_pairidx[N_PAIRS];
__device__ unsigned g_next;                        // work-stealing cursor
__device__ __half g_h  [(size_t)N_ATOMS * FDIM];  // 12.8 MB (h in fp16)
__device__ __half g_xh [(size_t)N_ATOMS * F3];    // 38.4 MB (x in fp16)
__device__ __half g_muh[(size_t)N_ATOMS * F3];    // 38.4 MB (mu in fp16)

// ---------------- small float4 helpers -------------------------------------
__device__ __forceinline__ float4 f4add(float4 a, float4 b) {
    return make_float4(a.x + b.x, a.y + b.y, a.z + b.z, a.w + b.w);
}
__device__ __forceinline__ float4 f4mul(float4 a, float4 b) {
    return make_float4(a.x * b.x, a.y * b.y, a.z * b.z, a.w * b.w);
}
__device__ __forceinline__ float4 f4fma(float4 a, float4 b, float4 c) {
    return make_float4(fmaf(a.x, b.x, c.x), fmaf(a.y, b.y, c.y),
                       fmaf(a.z, b.z, c.z), fmaf(a.w, b.w, c.w));
}
__device__ __forceinline__ float4 f4fmas(float4 a, float s, float4 c) {
    return make_float4(fmaf(a.x, s, c.x), fmaf(a.y, s, c.y),
                       fmaf(a.z, s, c.z), fmaf(a.w, s, c.w));
}
__device__ __forceinline__ float4 h4tof4(uint2 u) {
    __half2 a = *reinterpret_cast<__half2*>(&u.x);
    __half2 b = *reinterpret_cast<__half2*>(&u.y);
    float2 fa = __half22float2(a), fb = __half22float2(b);
    return make_float4(fa.x, fa.y, fb.x, fb.y);
}
__device__ __forceinline__ uint2 f4toh4(float4 v) {
    __half2 h0 = __floats2half2_rn(v.x, v.y);
    __half2 h1 = __floats2half2_rn(v.z, v.w);
    uint2 u;
    u.x = *reinterpret_cast<unsigned*>(&h0);
    u.y = *reinterpret_cast<unsigned*>(&h1);
    return u;
}

// ---------------- cp.async / cache-policy helpers ---------------------------
__device__ __forceinline__ unsigned smem_u32(const void* p) {
    return (unsigned)__cvta_generic_to_shared(p);
}
__device__ __forceinline__ unsigned long long mk_evict_first() {
    unsigned long long pol;
    asm("createpolicy.fractional.L2::evict_first.b64 %0, 1.0;" : "=l"(pol));
    return pol;
}
__device__ __forceinline__ unsigned long long mk_evict_last() {
    unsigned long long pol;
    asm("createpolicy.fractional.L2::evict_last.b64 %0, 1.0;" : "=l"(pol));
    return pol;
}
__device__ __forceinline__ void cp16_ef(unsigned d, const void* s, unsigned long long pol) {
    asm volatile("cp.async.cg.shared.global.L2::cache_hint [%0], [%1], 16, %2;"
                 :: "r"(d), "l"(s), "l"(pol));
}
__device__ __forceinline__ void cp_commit() {
    asm volatile("cp.async.commit_group;");
}
template<int N> __device__ __forceinline__ void cp_wait() {
    asm volatile("cp.async.wait_group %0;" :: "n"(N));
}
__device__ __forceinline__ uint2 ldg_el(const uint2* p, unsigned long long pol) {
    uint2 v;
    asm volatile("ld.global.nc.L2::cache_hint.v2.u32 {%0,%1}, [%2], %3;"
                 : "=r"(v.x), "=r"(v.y) : "l"(p), "l"(pol));
    return v;
}
__device__ __forceinline__ void stg_ef(float4* p, float4 v, unsigned long long pol) {
    asm volatile("st.global.L2::cache_hint.v4.f32 [%0], {%1,%2,%3,%4}, %5;"
                 :: "l"(p), "f"(v.x), "f"(v.y), "f"(v.z), "f"(v.w), "l"(pol));
}

// ---------------- CSR build -------------------------------------------------
__global__ void k_zero() {
    int i = blockIdx.x * blockDim.x + threadIdx.x;
    if (i < N_ATOMS) { g_count[i] = 0; g_cursor[i] = 0; }
    if (i == 0) g_next = 0;
}

__global__ void k_hist(const int* __restrict__ idx_i) {
    int p = blockIdx.x * blockDim.x + threadIdx.x;
    if (p < N_PAIRS) atomicAdd(&g_count[idx_i[p]], 1);
}

__global__ void k_scan() {
    __shared__ int warpsum[33];
    int lane = threadIdx.x & 31, wid = threadIdx.x >> 5;
    int running = 0;
    for (int base = 0; base < N_ATOMS; base += 1024) {
        int idx = base + (int)threadIdx.x;
        int v = (idx < N_ATOMS) ? g_count[idx] : 0;
        int incl = v;
        #pragma unroll
        for (int off = 1; off < 32; off <<= 1) {
            int t = __shfl_up_sync(0xffffffff, incl, off);
            if (lane >= off) incl += t;
        }
        if (lane == 31) warpsum[wid] = incl;
        __syncthreads();
        if (wid == 0) {
            int s = warpsum[lane];
            int si = s;
            #pragma unroll
            for (int off = 1; off < 32; off <<= 1) {
                int t = __shfl_up_sync(0xffffffff, si, off);
                if (lane >= off) si += t;
            }
            warpsum[lane] = si - s;
            if (lane == 31) warpsum[32] = si;
        }
        __syncthreads();
        if (idx < N_ATOMS) g_offset[idx] = running + warpsum[wid] + incl - v;
        running += warpsum[32];
        __syncthreads();
    }
    if (threadIdx.x == 0) g_offset[N_ATOMS] = running;
}

__global__ void k_scatter(const int* __restrict__ idx_i) {
    int p = blockIdx.x * blockDim.x + threadIdx.x;
    if (p < N_PAIRS) {
        int i = idx_i[p];
        int pos = atomicAdd(&g_cursor[i], 1);
        g_pairidx[g_offset[i] + pos] = p;
    }
}

// ---------------- mu -> fp16 mirror ----------------------------------------
__global__ void k_cvt_mu(const float* __restrict__ mu) {
    size_t i = (size_t)blockIdx.x * blockDim.x + threadIdx.x;
    size_t n4 = (size_t)N_ATOMS * F3 / 4;
    if (i >= n4) return;
    reinterpret_cast<uint2*>(g_muh)[i] = f4toh4(reinterpret_cast<const float4*>(mu)[i]);
}

// ---------------- fp16 tensor-core GEMM (m16n8k16, fp32 accum) -------------
__device__ __forceinline__ void mma_f16(float* d, const unsigned* a, const unsigned* b) {
    asm volatile(
        "mma.sync.aligned.m16n8k16.row.col.f32.f16.f16.f32 "
        "{%0,%1,%2,%3}, {%4,%5,%6,%7}, {%8,%9}, {%0,%1,%2,%3};"
        : "+f"(d[0]), "+f"(d[1]), "+f"(d[2]), "+f"(d[3])
        : "r"(a[0]), "r"(a[1]), "r"(a[2]), "r"(a[3]), "r"(b[0]), "r"(b[1]));
}

#define GBM 128
#define GBN 64
#define HSTRIDE 36   // uints per row (32 data + 4 pad)

template<bool IN_HALF, bool DO_SILU>
__global__ __launch_bounds__(256)
void gemm_tc(const void* __restrict__ Av, const float* __restrict__ W,
             const float* __restrict__ bias, __half* __restrict__ outh,
             int M, int N) {
    __shared__ unsigned As_h[GBM * HSTRIDE];
    __shared__ unsigned Ws_h[GBN * HSTRIDE];

    int tid  = threadIdx.x;
    int warp = tid >> 5, lane = tid & 31;
    int g = lane >> 2, t4 = lane & 3;
    int wm = warp >> 1, wn = warp & 1;
    int bm = blockIdx.y * GBM, bn = blockIdx.x * GBN;

    float acc[2][4][4];
    #pragma unroll
    for (int i = 0; i < 2; i++)
        #pragma unroll
        for (int j = 0; j < 4; j++)
            #pragma unroll
            for (int k = 0; k < 4; k++) acc[i][j][k] = 0.f;

    #pragma unroll
    for (int k0 = 0; k0 < 128; k0 += 64) {
        if (IN_HALF) {
            const uint2* A_h = reinterpret_cast<const uint2*>(Av);
            #pragma unroll
            for (int r = 0; r < 8; r++) {
                int t  = tid + r * 256;
                int ml = t >> 4, c = t & 15;
                uint2 v = make_uint2(0, 0);
                if (bm + ml < M) v = A_h[(size_t)(bm + ml) * 32 + k0 / 4 + c];
                *reinterpret_cast<uint2*>(As_h + ml * HSTRIDE + c * 2) = v;
            }
        } else {
            const float* A = reinterpret_cast<const float*>(Av);
            #pragma unroll
            for (int r = 0; r < 8; r++) {
                int t  = tid + r * 256;
                int ml = t >> 4, c = t & 15;
                float4 v = make_float4(0, 0, 0, 0);
                if (bm + ml < M) v = *reinterpret_cast<const float4*>(A + (size_t)(bm + ml) * 128 + k0 + c * 4);
                *reinterpret_cast<uint2*>(As_h + ml * HSTRIDE + c * 2) = f4toh4(v);
            }
        }
        #pragma unroll
        for (int r = 0; r < 4; r++) {
            int t  = tid + r * 256;
            int nl = t >> 4, c = t & 15;
            float4 v = *reinterpret_cast<const float4*>(W + (size_t)(bn + nl) * 128 + k0 + c * 4);
            *reinterpret_cast<uint2*>(Ws_h + nl * HSTRIDE + c * 2) = f4toh4(v);
        }
        __syncthreads();

        #pragma unroll
        for (int ks = 0; ks < 4; ks++) {
            int ku = ks * 8;
            unsigned a[2][4], b[4][2];
            #pragma unroll
            for (int tm = 0; tm < 2; tm++) {
                int mb = wm * 32 + tm * 16;
                const unsigned* r0 = As_h + (mb + g) * HSTRIDE + ku;
                const unsigned* r1 = As_h + (mb + 8 + g) * HSTRIDE + ku;
                a[tm][0] = r0[t4];     a[tm][1] = r1[t4];
                a[tm][2] = r0[t4 + 4]; a[tm][3] = r1[t4 + 4];
            }
            #pragma unroll
            for (int tn = 0; tn < 4; tn++) {
                int nb = wn * 32 + tn * 8;
                const unsigned* rw = Ws_h + (nb + g) * HSTRIDE + ku;
                b[tn][0] = rw[t4]; b[tn][1] = rw[t4 + 4];
            }
            #pragma unroll
            for (int tm = 0; tm < 2; tm++)
                #pragma unroll
                for (int tn = 0; tn < 4; tn++)
                    mma_f16(acc[tm][tn], a[tm], b[tn]);
        }
        __syncthreads();
    }

    #pragma unroll
    for (int tm = 0; tm < 2; tm++) {
        #pragma unroll
        for (int tn = 0; tn < 4; tn++) {
            int row0 = bm + wm * 32 + tm * 16 + g;
            int col  = bn + wn * 32 + tn * 8 + t4 * 2;
            float b0 = __ldg(bias + col), b1 = __ldg(bias + col + 1);
            float v0 = acc[tm][tn][0] + b0;
            float v1 = acc[tm][tn][1] + b1;
            float v2 = acc[tm][tn][2] + b0;
            float v3 = acc[tm][tn][3] + b1;
            if (DO_SILU) {
                v0 = v0 / (1.0f + __expf(-v0));
                v1 = v1 / (1.0f + __expf(-v1));
                v2 = v2 / (1.0f + __expf(-v2));
                v3 = v3 / (1.0f + __expf(-v3));
            }
            __half2 h01 = __floats2half2_rn(v0, v1);
            __half2 h23 = __floats2half2_rn(v2, v3);
            if (row0 < M)
                *reinterpret_cast<__half2*>(outh + (size_t)row0 * N + col) = h01;
            if (row0 + 8 < M)
                *reinterpret_cast<__half2*>(outh + (size_t)(row0 + 8) * N + col) = h23;
        }
    }
}

// ---------------- aggregation: persistent warps + asymmetric pipeline -------
// Work-stealing: each warp grabs batches of 4 consecutive atoms from g_next,
// eliminating the block-convoy idle (E[max of 4 segs] >> E[seg]).
// Wij -> cp.async ring depth 4 (L2 evict_first); x/mu -> reg ping-pong
// (L2 evict_last); out stores evict_first.
#define WDEPTH 4
#define MAXSEG 32
#define AGG_SMEM (24576 + 512 + 512 + 2048)
#define ABATCH 4

struct XM {
    uint2 x0, x1, x2, m0, m1, m2;
    float d0, d1, d2;
};

__global__ __launch_bounds__(128)
void k_agg(const float* __restrict__ q, const float* __restrict__ mu,
           const float* __restrict__ Wij, const float* __restrict__ dir,
           const int* __restrict__ idxj, float* __restrict__ out) {
    extern __shared__ char dsm[];
    int warp = threadIdx.x >> 5;
    int lane = threadIdx.x & 31;

    float4* sw = reinterpret_cast<float4*>(dsm)              + warp * (WDEPTH * 96);
    int*    sp = reinterpret_cast<int*>(dsm + 24576)         + warp * MAXSEG;
    int*    sj = reinterpret_cast<int*>(dsm + 24576 + 512)   + warp * MAXSEG;
    float4* sd = reinterpret_cast<float4*>(dsm + 24576 + 1024) + warp * MAXSEG;

    unsigned long long polEF = mk_evict_first();
    unsigned long long polEL = mk_evict_last();

    for (;;) {
        unsigned base = 0;
        if (lane == 0) base = atomicAdd(&g_next, ABATCH);
        base = __shfl_sync(0xffffffffu, base, 0);
        if (base >= N_ATOMS) return;
        unsigned iend = base + ABATCH; if (iend > N_ATOMS) iend = N_ATOMS;

        for (unsigned i = base; i < iend; ++i) {
            int s = g_offset[i], e = g_offset[i + 1];
            int n = e - s;

            // stage index/dir stream for this atom
            int nc = n < MAXSEG ? n : MAXSEG;
            __syncwarp();
            for (int t = lane; t < nc; t += 32) {
                int p = __ldg(g_pairidx + s + t);
                sp[t] = p;
                sj[t] = __ldg(idxj + p);
                sd[t] = make_float4(__ldg(dir + (size_t)p * 3 + 0),
                                    __ldg(dir + (size_t)p * 3 + 1),
                                    __ldg(dir + (size_t)p * 3 + 2), 0.f);
            }
            __syncwarp();

            float4 aq = make_float4(0, 0, 0, 0);
            float4 a0 = aq, a1 = aq, a2 = aq;

            auto issue_w = [&](int t) {
                if (t < n) {
                    int p = (t < MAXSEG) ? sp[t] : __ldg(g_pairidx + s + t);
                    int slot = t & (WDEPTH - 1);
                    const char* wsrc = (const char*)Wij + (size_t)p * 1536 + lane * 16;
                    unsigned wdst = smem_u32(sw + slot * 96 + lane);
                    cp16_ef(wdst,        wsrc,        polEF);
                    cp16_ef(wdst + 512,  wsrc + 512,  polEF);
                    cp16_ef(wdst + 1024, wsrc + 1024, polEF);
                }
                cp_commit();
            };

            auto load_xm = [&](XM& R, int t) {
                int p, j;
                if (t < MAXSEG) {
                    j = sj[t];
                    float4 dv = sd[t];
                    R.d0 = dv.x; R.d1 = dv.y; R.d2 = dv.z;
                } else {
                    p = __ldg(g_pairidx + s + t);
                    j = __ldg(idxj + p);
                    R.d0 = __ldg(dir + (size_t)p * 3 + 0);
                    R.d1 = __ldg(dir + (size_t)p * 3 + 1);
                    R.d2 = __ldg(dir + (size_t)p * 3 + 2);
                }
                const uint2* xp = reinterpret_cast<const uint2*>(g_xh)  + (size_t)j * 96;
                const uint2* mp = reinterpret_cast<const uint2*>(g_muh) + (size_t)j * 96;
                R.x0 = ldg_el(xp + lane, polEL);
                R.x1 = ldg_el(xp + lane + 32, polEL);
                R.x2 = ldg_el(xp + lane + 64, polEL);
                R.m0 = ldg_el(mp + lane, polEL);
                R.m1 = ldg_el(mp + lane + 32, polEL);
                R.m2 = ldg_el(mp + lane + 64, polEL);
            };

            auto accum = [&](const XM& R, int slot) {
                float4 w0 = sw[slot * 96 + lane];
                float4 w1 = sw[slot * 96 + lane + 32];
                float4 w2 = sw[slot * 96 + lane + 64];
                float4 x0 = h4tof4(R.x0), x1 = h4tof4(R.x1), x2 = h4tof4(R.x2);
                float4 m0 = h4tof4(R.m0), m1 = h4tof4(R.m1), m2 = h4tof4(R.m2);
                aq = f4fma(w0, x0, aq);
                float4 Rv = f4mul(w1, x1);
                float4 MM = f4mul(w2, x2);
                a0 = f4fma(MM, m0, f4fmas(Rv, R.d0, a0));
                a1 = f4fma(MM, m1, f4fmas(Rv, R.d1, a1));
                a2 = f4fma(MM, m2, f4fmas(Rv, R.d2, a2));
            };

            XM A, B;
            issue_w(0); issue_w(1); issue_w(2);
            if (n > 0) load_xm(A, 0);

            for (int t = 0; t < n; ) {
                issue_w(t + 3);
                if (t + 1 < n) load_xm(B, t + 1);
                cp_wait<WDEPTH - 1>();
                accum(A, t & (WDEPTH - 1));
                ++t;
                if (t >= n) break;

                issue_w(t + 3);
                if (t + 1 < n) load_xm(A, t + 1);
                cp_wait<WDEPTH - 1>();
                accum(B, t & (WDEPTH - 1));
                ++t;
            }

            const float4* qp = reinterpret_cast<const float4*>(q) + (size_t)i * 32;
            float4* oq = reinterpret_cast<float4*>(out) + (size_t)i * 32;
            stg_ef(oq + lane, f4add(qp[lane], aq), polEF);

            const float4* mup = reinterpret_cast<const float4*>(mu) + (size_t)i * 96;
            float4* om = reinterpret_cast<float4*>(out + (size_t)N_ATOMS * FDIM) + (size_t)i * 96;
            stg_ef(om + lane,      f4add(mup[lane],      a0), polEF);
            stg_ef(om + lane + 32, f4add(mup[lane + 32], a1), polEF);
            stg_ef(om + lane + 64, f4add(mup[lane + 64], a2), polEF);
        }
    }
}

// ---------------- launch ----------------------------------------------------
static cudaStream_t s_side = nullptr;
static cudaEvent_t  s_evFork = nullptr, s_evJoin = nullptr;

extern "C" void kernel_launch(void* const* d_in, const int* in_sizes, int n_in,
                              void* d_out, int out_size) {
    const float* q   = (const float*)d_in[0];
    const float* mu  = (const float*)d_in[1];
    const float* Wij = (const float*)d_in[2];
    const float* dir = (const float*)d_in[3];
    const int*   pl  = (const int*)d_in[4];
    const float* W1  = (const float*)d_in[5];
    const float* b1  = (const float*)d_in[6];
    const float* W2  = (const float*)d_in[7];
    const float* b2  = (const float*)d_in[8];
    float* out = (float*)d_out;

    const int* idx_i = pl;
    const int* idx_j = pl + N_PAIRS;

    __half *hbuf = nullptr, *xh = nullptr;
    cudaGetSymbolAddress((void**)&hbuf, g_h);
    cudaGetSymbolAddress((void**)&xh,   g_xh);

    if (!s_side) {
        cudaStreamCreateWithFlags(&s_side, cudaStreamNonBlocking);
        cudaEventCreateWithFlags(&s_evFork, cudaEventDisableTiming);
        cudaEventCreateWithFlags(&s_evJoin, cudaEventDisableTiming);
        cudaFuncSetAttribute(k_agg, cudaFuncAttributeMaxDynamicSharedMemorySize, AGG_SMEM);
    }

    // fork: CSR chain on side stream; cvt_mu + GEMM chain on main (balanced)
    cudaEventRecord(s_evFork, 0);
    cudaStreamWaitEvent(s_side, s_evFork, 0);

    k_zero   <<<(N_ATOMS + 255) / 256, 256, 0, s_side>>>();
    k_hist   <<<(N_PAIRS + 255) / 256, 256, 0, s_side>>>(idx_i);
    k_scan   <<<1, 1024, 0, s_side>>>();
    k_scatter<<<(N_PAIRS + 255) / 256, 256, 0, s_side>>>(idx_i);
    cudaEventRecord(s_evJoin, s_side);

    {
        size_t n4 = (size_t)N_ATOMS * F3 / 4;
        k_cvt_mu<<<(unsigned)((n4 + 255) / 256), 256>>>(mu);
    }
    dim3 g1(FDIM / GBN, (N_ATOMS + GBM - 1) / GBM);
    gemm_tc<false, true><<<g1, 256>>>(q, W1, b1, hbuf, N_ATOMS, FDIM);
    dim3 g2(F3 / GBN, (N_ATOMS + GBM - 1) / GBM);
    gemm_tc<true, false><<<g2, 256>>>(hbuf, W2, b2, xh, N_ATOMS, F3);

    // join, then aggregate (persistent grid: 8 blocks/SM x 152 SMs)
    cudaStreamWaitEvent(0, s_evJoin, 0);
    k_agg<<<152 * 8, 128, AGG_SMEM>>>(q, mu, Wij, dir, idx_j, out);
}

// round 17
// speedup vs baseline: 1.0179x; 1.0179x over previous
#include <cuda_runtime.h>
#include <cuda_fp16.h>

#define N_ATOMS 50000
#define N_PAIRS 800000
#define FDIM    128
#define F3      384

// ---------------- scratch (device globals; no runtime allocation) ----------
__device__ int    g_count [N_ATOMS];
__device__ int    g_cursor[N_ATOMS];
__device__ int    g_offset[N_ATOMS + 1];
__device__ int    g_pairidx[N_PAIRS];
__device__ int    g_dhist[64];
__device__ int    g_dbase[64];
__device__ int    g_dcur [64];
__device__ int    g_order[N_ATOMS];
__device__ __half g_h  [(size_t)N_ATOMS * FDIM];  // 12.8 MB (h in fp16)
__device__ __half g_xh [(size_t)N_ATOMS * F3];    // 38.4 MB (x in fp16)
__device__ __half g_muh[(size_t)N_ATOMS * F3];    // 38.4 MB (mu in fp16)

// ---------------- small float4 helpers -------------------------------------
__device__ __forceinline__ float4 f4add(float4 a, float4 b) {
    return make_float4(a.x + b.x, a.y + b.y, a.z + b.z, a.w + b.w);
}
__device__ __forceinline__ float4 f4mul(float4 a, float4 b) {
    return make_float4(a.x * b.x, a.y * b.y, a.z * b.z, a.w * b.w);
}
__device__ __forceinline__ float4 f4fma(float4 a, float4 b, float4 c) {
    return make_float4(fmaf(a.x, b.x, c.x), fmaf(a.y, b.y, c.y),
                       fmaf(a.z, b.z, c.z), fmaf(a.w, b.w, c.w));
}
__device__ __forceinline__ float4 f4fmas(float4 a, float s, float4 c) {
    return make_float4(fmaf(a.x, s, c.x), fmaf(a.y, s, c.y),
                       fmaf(a.z, s, c.z), fmaf(a.w, s, c.w));
}
__device__ __forceinline__ float4 h4tof4(uint2 u) {
    __half2 a = *reinterpret_cast<__half2*>(&u.x);
    __half2 b = *reinterpret_cast<__half2*>(&u.y);
    float2 fa = __half22float2(a), fb = __half22float2(b);
    return make_float4(fa.x, fa.y, fb.x, fb.y);
}
__device__ __forceinline__ uint2 f4toh4(float4 v) {
    __half2 h0 = __floats2half2_rn(v.x, v.y);
    __half2 h1 = __floats2half2_rn(v.z, v.w);
    uint2 u;
    u.x = *reinterpret_cast<unsigned*>(&h0);
    u.y = *reinterpret_cast<unsigned*>(&h1);
    return u;
}

// ---------------- cp.async / cache-policy helpers ---------------------------
__device__ __forceinline__ unsigned smem_u32(const void* p) {
    return (unsigned)__cvta_generic_to_shared(p);
}
__device__ __forceinline__ unsigned long long mk_evict_first() {
    unsigned long long pol;
    asm("createpolicy.fractional.L2::evict_first.b64 %0, 1.0;" : "=l"(pol));
    return pol;
}
__device__ __forceinline__ unsigned long long mk_evict_last() {
    unsigned long long pol;
    asm("createpolicy.fractional.L2::evict_last.b64 %0, 1.0;" : "=l"(pol));
    return pol;
}
__device__ __forceinline__ void cp16_ef(unsigned d, const void* s, unsigned long long pol) {
    asm volatile("cp.async.cg.shared.global.L2::cache_hint [%0], [%1], 16, %2;"
                 :: "r"(d), "l"(s), "l"(pol));
}
__device__ __forceinline__ void cp_commit() {
    asm volatile("cp.async.commit_group;");
}
template<int N> __device__ __forceinline__ void cp_wait() {
    asm volatile("cp.async.wait_group %0;" :: "n"(N));
}
__device__ __forceinline__ uint2 ldg_el(const uint2* p, unsigned long long pol) {
    uint2 v;
    asm volatile("ld.global.nc.L2::cache_hint.v2.u32 {%0,%1}, [%2], %3;"
                 : "=r"(v.x), "=r"(v.y) : "l"(p), "l"(pol));
    return v;
}
__device__ __forceinline__ void stg_ef(float4* p, float4 v, unsigned long long pol) {
    asm volatile("st.global.L2::cache_hint.v4.f32 [%0], {%1,%2,%3,%4}, %5;"
                 :: "l"(p), "f"(v.x), "f"(v.y), "f"(v.z), "f"(v.w), "l"(pol));
}

// ---------------- CSR build + degree sort -----------------------------------
__global__ void k_zero() {
    int i = blockIdx.x * blockDim.x + threadIdx.x;
    if (i < N_ATOMS) { g_count[i] = 0; g_cursor[i] = 0; }
    if (i < 64) { g_dhist[i] = 0; g_dcur[i] = 0; }
}

__global__ void k_hist(const int* __restrict__ idx_i) {
    int p = blockIdx.x * blockDim.x + threadIdx.x;
    if (p < N_PAIRS) atomicAdd(&g_count[idx_i[p]], 1);
}

__global__ void k_dhist() {
    int i = blockIdx.x * blockDim.x + threadIdx.x;
    if (i < N_ATOMS) {
        int d = g_count[i]; if (d > 63) d = 63;
        atomicAdd(&g_dhist[d], 1);
    }
}

__global__ void k_dscan() {
    if (threadIdx.x == 0) {
        int run = 0;
        for (int k = 0; k < 64; k++) { g_dbase[k] = run; run += g_dhist[k]; }
    }
}

__global__ void k_dscatter() {
    int i = blockIdx.x * blockDim.x + threadIdx.x;
    if (i < N_ATOMS) {
        int d = g_count[i]; if (d > 63) d = 63;
        int pos = atomicAdd(&g_dcur[d], 1);
        g_order[g_dbase[d] + pos] = i;
    }
}

__global__ void k_scan() {
    __shared__ int warpsum[33];
    int lane = threadIdx.x & 31, wid = threadIdx.x >> 5;
    int running = 0;
    for (int base = 0; base < N_ATOMS; base += 1024) {
        int idx = base + (int)threadIdx.x;
        int v = (idx < N_ATOMS) ? g_count[idx] : 0;
        int incl = v;
        #pragma unroll
        for (int off = 1; off < 32; off <<= 1) {
            int t = __shfl_up_sync(0xffffffff, incl, off);
            if (lane >= off) incl += t;
        }
        if (lane == 31) warpsum[wid] = incl;
        __syncthreads();
        if (wid == 0) {
            int s = warpsum[lane];
            int si = s;
            #pragma unroll
            for (int off = 1; off < 32; off <<= 1) {
                int t = __shfl_up_sync(0xffffffff, si, off);
                if (lane >= off) si += t;
            }
            warpsum[lane] = si - s;
            if (lane == 31) warpsum[32] = si;
        }
        __syncthreads();
        if (idx < N_ATOMS) g_offset[idx] = running + warpsum[wid] + incl - v;
        running += warpsum[32];
        __syncthreads();
    }
    if (threadIdx.x == 0) g_offset[N_ATOMS] = running;
}

__global__ void k_scatter(const int* __restrict__ idx_i) {
    int p = blockIdx.x * blockDim.x + threadIdx.x;
    if (p < N_PAIRS) {
        int i = idx_i[p];
        int pos = atomicAdd(&g_cursor[i], 1);
        g_pairidx[g_offset[i] + pos] = p;
    }
}

// ---------------- mu -> fp16 mirror ----------------------------------------
__global__ void k_cvt_mu(const float* __restrict__ mu) {
    size_t i = (size_t)blockIdx.x * blockDim.x + threadIdx.x;
    size_t n4 = (size_t)N_ATOMS * F3 / 4;
    if (i >= n4) return;
    reinterpret_cast<uint2*>(g_muh)[i] = f4toh4(reinterpret_cast<const float4*>(mu)[i]);
}

// ---------------- fp16 tensor-core GEMM (m16n8k16, fp32 accum) -------------
__device__ __forceinline__ void mma_f16(float* d, const unsigned* a, const unsigned* b) {
    asm volatile(
        "mma.sync.aligned.m16n8k16.row.col.f32.f16.f16.f32 "
        "{%0,%1,%2,%3}, {%4,%5,%6,%7}, {%8,%9}, {%0,%1,%2,%3};"
        : "+f"(d[0]), "+f"(d[1]), "+f"(d[2]), "+f"(d[3])
        : "r"(a[0]), "r"(a[1]), "r"(a[2]), "r"(a[3]), "r"(b[0]), "r"(b[1]));
}

#define GBM 128
#define GBN 64
#define HSTRIDE 36   // uints per row (32 data + 4 pad)

template<bool IN_HALF, bool DO_SILU>
__global__ __launch_bounds__(256)
void gemm_tc(const void* __restrict__ Av, const float* __restrict__ W,
             const float* __restrict__ bias, __half* __restrict__ outh,
             int M, int N) {
    __shared__ unsigned As_h[GBM * HSTRIDE];
    __shared__ unsigned Ws_h[GBN * HSTRIDE];

    int tid  = threadIdx.x;
    int warp = tid >> 5, lane = tid & 31;
    int g = lane >> 2, t4 = lane & 3;
    int wm = warp >> 1, wn = warp & 1;
    int bm = blockIdx.y * GBM, bn = blockIdx.x * GBN;

    float acc[2][4][4];
    #pragma unroll
    for (int i = 0; i < 2; i++)
        #pragma unroll
        for (int j = 0; j < 4; j++)
            #pragma unroll
            for (int k = 0; k < 4; k++) acc[i][j][k] = 0.f;

    #pragma unroll
    for (int k0 = 0; k0 < 128; k0 += 64) {
        if (IN_HALF) {
            const uint2* A_h = reinterpret_cast<const uint2*>(Av);
            #pragma unroll
            for (int r = 0; r < 8; r++) {
                int t  = tid + r * 256;
                int ml = t >> 4, c = t & 15;
                uint2 v = make_uint2(0, 0);
                if (bm + ml < M) v = A_h[(size_t)(bm + ml) * 32 + k0 / 4 + c];
                *reinterpret_cast<uint2*>(As_h + ml * HSTRIDE + c * 2) = v;
            }
        } else {
            const float* A = reinterpret_cast<const float*>(Av);
            #pragma unroll
            for (int r = 0; r < 8; r++) {
                int t  = tid + r * 256;
                int ml = t >> 4, c = t & 15;
                float4 v = make_float4(0, 0, 0, 0);
                if (bm + ml < M) v = *reinterpret_cast<const float4*>(A + (size_t)(bm + ml) * 128 + k0 + c * 4);
                *reinterpret_cast<uint2*>(As_h + ml * HSTRIDE + c * 2) = f4toh4(v);
            }
        }
        #pragma unroll
        for (int r = 0; r < 4; r++) {
            int t  = tid + r * 256;
            int nl = t >> 4, c = t & 15;
            float4 v = *reinterpret_cast<const float4*>(W + (size_t)(bn + nl) * 128 + k0 + c * 4);
            *reinterpret_cast<uint2*>(Ws_h + nl * HSTRIDE + c * 2) = f4toh4(v);
        }
        __syncthreads();

        #pragma unroll
        for (int ks = 0; ks < 4; ks++) {
            int ku = ks * 8;
            unsigned a[2][4], b[4][2];
            #pragma unroll
            for (int tm = 0; tm < 2; tm++) {
                int mb = wm * 32 + tm * 16;
                const unsigned* r0 = As_h + (mb + g) * HSTRIDE + ku;
                const unsigned* r1 = As_h + (mb + 8 + g) * HSTRIDE + ku;
                a[tm][0] = r0[t4];     a[tm][1] = r1[t4];
                a[tm][2] = r0[t4 + 4]; a[tm][3] = r1[t4 + 4];
            }
            #pragma unroll
            for (int tn = 0; tn < 4; tn++) {
                int nb = wn * 32 + tn * 8;
                const unsigned* rw = Ws_h + (nb + g) * HSTRIDE + ku;
                b[tn][0] = rw[t4]; b[tn][1] = rw[t4 + 4];
            }
            #pragma unroll
            for (int tm = 0; tm < 2; tm++)
                #pragma unroll
                for (int tn = 0; tn < 4; tn++)
                    mma_f16(acc[tm][tn], a[tm], b[tn]);
        }
        __syncthreads();
    }

    #pragma unroll
    for (int tm = 0; tm < 2; tm++) {
        #pragma unroll
        for (int tn = 0; tn < 4; tn++) {
            int row0 = bm + wm * 32 + tm * 16 + g;
            int col  = bn + wn * 32 + tn * 8 + t4 * 2;
            float b0 = __ldg(bias + col), b1 = __ldg(bias + col + 1);
            float v0 = acc[tm][tn][0] + b0;
            float v1 = acc[tm][tn][1] + b1;
            float v2 = acc[tm][tn][2] + b0;
            float v3 = acc[tm][tn][3] + b1;
            if (DO_SILU) {
                v0 = v0 / (1.0f + __expf(-v0));
                v1 = v1 / (1.0f + __expf(-v1));
                v2 = v2 / (1.0f + __expf(-v2));
                v3 = v3 / (1.0f + __expf(-v3));
            }
            __half2 h01 = __floats2half2_rn(v0, v1);
            __half2 h23 = __floats2half2_rn(v2, v3);
            if (row0 < M)
                *reinterpret_cast<__half2*>(outh + (size_t)row0 * N + col) = h01;
            if (row0 + 8 < M)
                *reinterpret_cast<__half2*>(outh + (size_t)(row0 + 8) * N + col) = h23;
        }
    }
}

// ---------------- aggregation: R14 pipeline + degree-sorted atom order ------
// Warps within a block now process atoms of (nearly) equal degree, so block
// retirement time ~ mean instead of max-of-4 -> convoy idle removed.
#define WDEPTH 4
#define MAXSEG 32
#define AGG_SMEM (24576 + 512 + 512 + 2048)

struct XM {
    uint2 x0, x1, x2, m0, m1, m2;
    float d0, d1, d2;
};

__global__ __launch_bounds__(128)
void k_agg(const float* __restrict__ q, const float* __restrict__ mu,
           const float* __restrict__ Wij, const float* __restrict__ dir,
           const int* __restrict__ idxj, float* __restrict__ out) {
    extern __shared__ char dsm[];
    int warp = threadIdx.x >> 5;
    int lane = threadIdx.x & 31;

    float4* sw = reinterpret_cast<float4*>(dsm)              + warp * (WDEPTH * 96);
    int*    sp = reinterpret_cast<int*>(dsm + 24576)         + warp * MAXSEG;
    int*    sj = reinterpret_cast<int*>(dsm + 24576 + 512)   + warp * MAXSEG;
    float4* sd = reinterpret_cast<float4*>(dsm + 24576 + 1024) + warp * MAXSEG;

    int slotIdx = blockIdx.x * 4 + warp;
    if (slotIdx >= N_ATOMS) return;
    int i = g_order[slotIdx];

    unsigned long long polEF = mk_evict_first();
    unsigned long long polEL = mk_evict_last();

    int s = g_offset[i], e = g_offset[i + 1];
    int n = e - s;

    int nc = n < MAXSEG ? n : MAXSEG;
    for (int t = lane; t < nc; t += 32) {
        int p = __ldg(g_pairidx + s + t);
        sp[t] = p;
        sj[t] = __ldg(idxj + p);
        sd[t] = make_float4(__ldg(dir + (size_t)p * 3 + 0),
                            __ldg(dir + (size_t)p * 3 + 1),
                            __ldg(dir + (size_t)p * 3 + 2), 0.f);
    }
    __syncwarp();

    float4 aq = make_float4(0, 0, 0, 0);
    float4 a0 = aq, a1 = aq, a2 = aq;

    auto issue_w = [&](int t) {
        if (t < n) {
            int p = (t < MAXSEG) ? sp[t] : __ldg(g_pairidx + s + t);
            int slot = t & (WDEPTH - 1);
            const char* wsrc = (const char*)Wij + (size_t)p * 1536 + lane * 16;
            unsigned wdst = smem_u32(sw + slot * 96 + lane);
            cp16_ef(wdst,        wsrc,        polEF);
            cp16_ef(wdst + 512,  wsrc + 512,  polEF);
            cp16_ef(wdst + 1024, wsrc + 1024, polEF);
        }
        cp_commit();
    };

    auto load_xm = [&](XM& R, int t) {
        int p, j;
        if (t < MAXSEG) {
            j = sj[t];
            float4 dv = sd[t];
            R.d0 = dv.x; R.d1 = dv.y; R.d2 = dv.z;
        } else {
            p = __ldg(g_pairidx + s + t);
            j = __ldg(idxj + p);
            R.d0 = __ldg(dir + (size_t)p * 3 + 0);
            R.d1 = __ldg(dir + (size_t)p * 3 + 1);
            R.d2 = __ldg(dir + (size_t)p * 3 + 2);
        }
        const uint2* xp = reinterpret_cast<const uint2*>(g_xh)  + (size_t)j * 96;
        const uint2* mp = reinterpret_cast<const uint2*>(g_muh) + (size_t)j * 96;
        R.x0 = ldg_el(xp + lane, polEL);
        R.x1 = ldg_el(xp + lane + 32, polEL);
        R.x2 = ldg_el(xp + lane + 64, polEL);
        R.m0 = ldg_el(mp + lane, polEL);
        R.m1 = ldg_el(mp + lane + 32, polEL);
        R.m2 = ldg_el(mp + lane + 64, polEL);
    };

    auto accum = [&](const XM& R, int slot) {
        float4 w0 = sw[slot * 96 + lane];
        float4 w1 = sw[slot * 96 + lane + 32];
        float4 w2 = sw[slot * 96 + lane + 64];
        float4 x0 = h4tof4(R.x0), x1 = h4tof4(R.x1), x2 = h4tof4(R.x2);
        float4 m0 = h4tof4(R.m0), m1 = h4tof4(R.m1), m2 = h4tof4(R.m2);
        aq = f4fma(w0, x0, aq);
        float4 Rv = f4mul(w1, x1);
        float4 MM = f4mul(w2, x2);
        a0 = f4fma(MM, m0, f4fmas(Rv, R.d0, a0));
        a1 = f4fma(MM, m1, f4fmas(Rv, R.d1, a1));
        a2 = f4fma(MM, m2, f4fmas(Rv, R.d2, a2));
    };

    XM A, B;
    issue_w(0); issue_w(1); issue_w(2);
    if (n > 0) load_xm(A, 0);

    for (int t = 0; t < n; ) {
        issue_w(t + 3);
        if (t + 1 < n) load_xm(B, t + 1);
        cp_wait<WDEPTH - 1>();
        accum(A, t & (WDEPTH - 1));
        ++t;
        if (t >= n) break;

        issue_w(t + 3);
        if (t + 1 < n) load_xm(A, t + 1);
        cp_wait<WDEPTH - 1>();
        accum(B, t & (WDEPTH - 1));
        ++t;
    }

    const float4* qp = reinterpret_cast<const float4*>(q) + (size_t)i * 32;
    float4* oq = reinterpret_cast<float4*>(out) + (size_t)i * 32;
    stg_ef(oq + lane, f4add(qp[lane], aq), polEF);

    const float4* mup = reinterpret_cast<const float4*>(mu) + (size_t)i * 96;
    float4* om = reinterpret_cast<float4*>(out + (size_t)N_ATOMS * FDIM) + (size_t)i * 96;
    stg_ef(om + lane,      f4add(mup[lane],      a0), polEF);
    stg_ef(om + lane + 32, f4add(mup[lane + 32], a1), polEF);
    stg_ef(om + lane + 64, f4add(mup[lane + 64], a2), polEF);
}

// ---------------- launch ----------------------------------------------------
static cudaStream_t s_side = nullptr;
static cudaEvent_t  s_evFork = nullptr, s_evJoin = nullptr;

extern "C" void kernel_launch(void* const* d_in, const int* in_sizes, int n_in,
                              void* d_out, int out_size) {
    const float* q   = (const float*)d_in[0];
    const float* mu  = (const float*)d_in[1];
    const float* Wij = (const float*)d_in[2];
    const float* dir = (const float*)d_in[3];
    const int*   pl  = (const int*)d_in[4];
    const float* W1  = (const float*)d_in[5];
    const float* b1  = (const float*)d_in[6];
    const float* W2  = (const float*)d_in[7];
    const float* b2  = (const float*)d_in[8];
    float* out = (float*)d_out;

    const int* idx_i = pl;
    const int* idx_j = pl + N_PAIRS;

    __half *hbuf = nullptr, *xh = nullptr;
    cudaGetSymbolAddress((void**)&hbuf, g_h);
    cudaGetSymbolAddress((void**)&xh,   g_xh);

    if (!s_side) {
        cudaStreamCreateWithFlags(&s_side, cudaStreamNonBlocking);
        cudaEventCreateWithFlags(&s_evFork, cudaEventDisableTiming);
        cudaEventCreateWithFlags(&s_evJoin, cudaEventDisableTiming);
        cudaFuncSetAttribute(k_agg, cudaFuncAttributeMaxDynamicSharedMemorySize, AGG_SMEM);
    }

    // fork: CSR + degree-sort chain on side stream; cvt_mu + GEMMs on main
    cudaEventRecord(s_evFork, 0);
    cudaStreamWaitEvent(s_side, s_evFork, 0);

    k_zero    <<<(N_ATOMS + 255) / 256, 256, 0, s_side>>>();
    k_hist    <<<(N_PAIRS + 255) / 256, 256, 0, s_side>>>(idx_i);
    k_dhist   <<<(N_ATOMS + 255) / 256, 256, 0, s_side>>>();
    k_scan    <<<1, 1024, 0, s_side>>>();
    k_dscan   <<<1, 32, 0, s_side>>>();
    k_scatter <<<(N_PAIRS + 255) / 256, 256, 0, s_side>>>(idx_i);
    k_dscatter<<<(N_ATOMS + 255) / 256, 256, 0, s_side>>>();
    cudaEventRecord(s_evJoin, s_side);

    {
        size_t n4 = (size_t)N_ATOMS * F3 / 4;
        k_cvt_mu<<<(unsigned)((n4 + 255) / 256), 256>>>(mu);
    }
    dim3 g1(FDIM / GBN, (N_ATOMS + GBM - 1) / GBM);
    gemm_tc<false, true><<<g1, 256>>>(q, W1, b1, hbuf, N_ATOMS, FDIM);
    dim3 g2(F3 / GBN, (N_ATOMS + GBM - 1) / GBM);
    gemm_tc<true, false><<<g2, 256>>>(hbuf, W2, b2, xh, N_ATOMS, F3);

    // join, then aggregate (degree-sorted order)
    cudaStreamWaitEvent(0, s_evJoin, 0);
    k_agg<<<(N_ATOMS + 3) / 4, 128, AGG_SMEM>>>(q, mu, Wij, dir, idx_j, out);
}